// round 15
// baseline (speedup 1.0000x reference)
#include <cuda_runtime.h>
#include <cuda_fp16.h>
#include <math.h>
#include <stdint.h>

#define BB   2
#define SS   2048
#define DD   2048
#define HQ   32
#define HKV  8
#define DH   64
#define KDIM 2048

// ---------------------------------------------------------------------------
// Scratch (allocation-free rule: __device__ globals) — pure fp16 pipeline
// ---------------------------------------------------------------------------
__device__ __half g_Xh[(size_t)BB * SS * DD];
__device__ __half g_Wqh[(size_t)HQ * DH * DD];
__device__ __half g_Wkh[(size_t)HKV * DH * DD];
__device__ __half g_Wvh[(size_t)HKV * DH * DD];
__device__ __half g_Woh[(size_t)DD * DD];
__device__ __half g_Oh[(size_t)BB * SS * DD];

__device__ __half g_Qbh[(size_t)BB * HQ  * SS * DH];
__device__ __half g_Kbh[(size_t)BB * HKV * SS * DH];
__device__ __half g_Vbh[(size_t)BB * HKV * SS * DH];

// ---------------------------------------------------------------------------
// helpers
// ---------------------------------------------------------------------------
__device__ __forceinline__ uint32_t s2u(const void* p) {
    uint32_t r;
    asm("{ .reg .u64 t; cvta.to.shared.u64 t, %1; cvt.u32.u64 %0, t; }"
        : "=r"(r) : "l"(p));
    return r;
}

#define LDM4(r, addr)                                                         \
    asm volatile("ldmatrix.sync.aligned.m8n8.x4.shared.b16 {%0,%1,%2,%3}, [%4];" \
        : "=r"((r)[0]), "=r"((r)[1]), "=r"((r)[2]), "=r"((r)[3]) : "r"(addr))

#define LDM4T(r, addr)                                                        \
    asm volatile("ldmatrix.sync.aligned.m8n8.x4.trans.shared.b16 {%0,%1,%2,%3}, [%4];" \
        : "=r"((r)[0]), "=r"((r)[1]), "=r"((r)[2]), "=r"((r)[3]) : "r"(addr))

#define MMA_F16(c, a, b0, b1)                                                 \
    asm volatile("mma.sync.aligned.m16n8k16.row.col.f32.f16.f16.f32 "         \
        "{%0,%1,%2,%3}, {%4,%5,%6,%7}, {%8,%9}, {%0,%1,%2,%3};"               \
        : "+f"((c)[0]), "+f"((c)[1]), "+f"((c)[2]), "+f"((c)[3])              \
        : "r"((a)[0]), "r"((a)[1]), "r"((a)[2]), "r"((a)[3]), "r"(b0), "r"(b1))

#define CP_ASYNC16(dst, src)                                                  \
    asm volatile("cp.async.cg.shared.global [%0], [%1], 16;" :: "r"(dst), "l"(src))

__device__ __forceinline__ uint32_t pack_h2(float a, float b) {
    __half2 t = __floats2half2_rn(a, b);
    return *reinterpret_cast<uint32_t*>(&t);
}

// ---------------------------------------------------------------------------
// merged input converts: one launch, fp32 -> fp16 for all five inputs
// ---------------------------------------------------------------------------
struct SplitJobs {
    const float4* in[5];
    __half2* hi[5];
    int blk_end[5];
};

__global__ void split_all(SplitJobs jobs)
{
    int bx = blockIdx.x;
    int job = 0;
#pragma unroll
    for (int k = 0; k < 5; ++k)
        if (bx >= jobs.blk_end[k]) job = k + 1;
    int blk0 = (job == 0) ? 0 : jobs.blk_end[job - 1];
    int i = (bx - blk0) * blockDim.x + threadIdx.x;

    float4 a = jobs.in[job][i];
    jobs.hi[job][2 * i + 0] = __floats2half2_rn(a.x, a.y);
    jobs.hi[job][2 * i + 1] = __floats2half2_rn(a.z, a.w);
}

// ---------------------------------------------------------------------------
// core fp16 MMA loop (CTA 128x128x2048), 1-term
// 4 warps, warp tile 64x64. Stage = {Ah, Bh} = 16KB.
// XOR-swizzled smem (64B rows), 6-stage ring, TWO stages per wait+sync
// (32 barriers instead of 64), 96KB -> 2 CTAs/SM.
// ---------------------------------------------------------------------------
#define MATB   8192                 // 128 rows * 64 B
#define STAGEB 16384                // 2 * MATB
#define GSTG   6
#define KITERS (KDIM / 32)          // 64 stages
#define NPAIR  (KITERS / 2)         // 32 sync iterations

struct GemmCore {
    float c[4][8][4];
};

__device__ __forceinline__ void gemm_mainloop(
    uint32_t sb, int tid, int lane, int wm, int wn,
    const __half* Ah_g, const __half* Bh_g,
    int m0, int n0, GemmCore& g)
{
#pragma unroll
    for (int i = 0; i < 4; ++i)
#pragma unroll
        for (int j = 0; j < 8; ++j)
#pragma unroll
            for (int r = 0; r < 4; ++r) g.c[i][j][r] = 0.f;

    const int a_row = wm * 64 + (lane & 15);
    const uint32_t a_base = (uint32_t)a_row * 64;
    const uint32_t a_swz  = (uint32_t)(((lane >> 4) ^ ((a_row >> 1) & 3)) << 4);

    const int b_row = wn * 64 + (lane >> 4) * 8 + (lane & 7);
    const uint32_t b_base = (uint32_t)b_row * 64;
    const uint32_t b_swz  = (uint32_t)((((lane >> 3) & 1) ^ ((b_row >> 1) & 3)) << 4);

    const __half* srcs[2] = { Ah_g, Bh_g };
    const int rowbase[2] = { m0, n0 };

    auto load_stage = [&](int s, int k0) {
#pragma unroll
        for (int i = 0; i < 8; ++i) {
            const int idx = tid + 128 * i;
            const int mat = idx >> 9;
            const int rem = idx & 511;
            const int row = rem >> 2;
            const int seg = rem & 3;
            uint32_t d = sb + s * STAGEB + mat * MATB + row * 64 +
                         ((seg ^ ((row >> 1) & 3)) << 4);
            const __half* p =
                srcs[mat] + (size_t)(rowbase[mat] + row) * KDIM + k0 + seg * 8;
            CP_ASYNC16(d, p);
        }
        asm volatile("cp.async.commit_group;");
    };

    load_stage(0, 0);
    load_stage(1, 32);
    load_stage(2, 64);
    load_stage(3, 96);

    for (int p = 0; p < NPAIR; ++p) {
        if (2 * p + 3 < KITERS) {
            asm volatile("cp.async.wait_group 2;");
        } else {
            asm volatile("cp.async.wait_group 0;");
        }
        __syncthreads();
        if (2 * p + 4 < KITERS) load_stage((2 * p + 4) % GSTG, (2 * p + 4) * 32);
        if (2 * p + 5 < KITERS) load_stage((2 * p + 5) % GSTG, (2 * p + 5) * 32);

#pragma unroll
        for (int hs = 0; hs < 2; ++hs) {
            const uint32_t st = sb + ((2 * p + hs) % GSTG) * STAGEB;
#pragma unroll
            for (int kk = 0; kk < 2; ++kk) {
                const uint32_t ksw = (uint32_t)(kk << 5);
                uint32_t bh[4][4];
#pragma unroll
                for (int j2 = 0; j2 < 4; ++j2) {
                    LDM4(bh[j2], st + MATB + b_base + j2 * 1024 + (b_swz ^ ksw));
                }
#pragma unroll
                for (int i = 0; i < 4; ++i) {
                    uint32_t ah[4];
                    LDM4(ah, st + a_base + i * 1024 + (a_swz ^ ksw));
#pragma unroll
                    for (int j = 0; j < 8; ++j) {
                        const uint32_t* bhp = &bh[j >> 1][(j & 1) * 2];
                        MMA_F16(g.c[i][j], ah, bhp[0], bhp[1]);
                    }
                }
            }
        }
    }
}

// ---------------------------------------------------------------------------
// merged QKV projection: grid (24, 32), 128 threads, all 1-term
// ---------------------------------------------------------------------------
__global__ __launch_bounds__(128, 2)
void qkv_gemm(const __half* __restrict__ Xh_g,
              const __half* __restrict__ Wqh_g,
              const __half* __restrict__ Wkh_g,
              const __half* __restrict__ Wvh_g,
              __half* __restrict__ Qh,
              __half* __restrict__ Kh,
              __half* __restrict__ Vh)
{
    extern __shared__ __align__(128) char smem[];
    const uint32_t sb = s2u(smem);

    const int tid  = threadIdx.x;
    const int lane = tid & 31;
    const int w    = tid >> 5;
    const int wm   = w & 1;
    const int wn   = w >> 1;
    const int bx   = blockIdx.x;
    const int m0   = blockIdx.y * 128;

    const __half *Bh_g;
    __half *dH;
    int n0, Hn;
    bool rope;
    float scale;
    if (bx < 16) {
        Bh_g = Wqh_g; dH = Qh;
        n0 = bx * 128; Hn = HQ; rope = true; scale = 0.125f;
    } else if (bx < 20) {
        Bh_g = Wkh_g; dH = Kh;
        n0 = (bx - 16) * 128; Hn = HKV; rope = true; scale = 1.0f;
    } else {
        Bh_g = Wvh_g; dH = Vh;
        n0 = (bx - 20) * 128; Hn = HKV; rope = false; scale = 1.0f;
    }

    GemmCore g;
    gemm_mainloop(sb, tid, lane, wm, wn, Xh_g, Bh_g, m0, n0, g);

#pragma unroll
    for (int i = 0; i < 4; ++i) {
        const int r0 = m0 + wm * 64 + i * 16 + (lane >> 2);
#pragma unroll
        for (int j = 0; j < 8; ++j) {
            const int col = n0 + wn * 64 + j * 8 + (lane & 3) * 2;
#pragma unroll
            for (int half = 0; half < 2; ++half) {
                const int row = r0 + half * 8;
                float x1 = g.c[i][j][half * 2];
                float x2 = g.c[i][j][half * 2 + 1];
                const int bidx = row >> 11;
                const int sRow = row & (SS - 1);
                const int hh = col >> 6, d0 = col & 63;
                size_t base = ((((size_t)bidx * Hn + hh) * SS + sRow) << 6) + d0;
                if (rope) {
                    float inv = exp2f(-(float)d0 * (13.287712379549449f / 64.0f));
                    float sn, cs;
                    sincosf((float)sRow * inv, &sn, &cs);
                    float y1 = x1 * cs - x2 * sn;
                    float y2 = x1 * sn + x2 * cs;
                    x1 = y1 * scale;
                    x2 = y2 * scale;
                }
                *reinterpret_cast<__half2*>(dH + base) =
                    __floats2half2_rn(x1, x2);
            }
        }
    }
}

// ---------------------------------------------------------------------------
// output projection (1-term fp16): fp32 flat result, 128 threads
// ---------------------------------------------------------------------------
__global__ __launch_bounds__(128, 2)
void wo_gemm(const __half* __restrict__ Ah_g,
             const __half* __restrict__ Bh_g,
             float* __restrict__ dst)
{
    extern __shared__ __align__(128) char smem[];
    const uint32_t sb = s2u(smem);

    const int tid  = threadIdx.x;
    const int lane = tid & 31;
    const int w    = tid >> 5;
    const int wm   = w & 1;
    const int wn   = w >> 1;
    const int m0   = blockIdx.y * 128;
    const int n0   = blockIdx.x * 128;

    GemmCore g;
    gemm_mainloop(sb, tid, lane, wm, wn, Ah_g, Bh_g, m0, n0, g);

#pragma unroll
    for (int i = 0; i < 4; ++i) {
        const int r0 = m0 + wm * 64 + i * 16 + (lane >> 2);
#pragma unroll
        for (int j = 0; j < 8; ++j) {
            const int col = n0 + wn * 64 + j * 8 + (lane & 3) * 2;
#pragma unroll
            for (int half = 0; half < 2; ++half) {
                const int row = r0 + half * 8;
                *reinterpret_cast<float2*>(dst + (size_t)row * DD + col) =
                    make_float2(g.c[i][j][half * 2], g.c[i][j][half * 2 + 1]);
            }
        }
    }
}

// ---------------------------------------------------------------------------
// MMA flash attention (causal, GQA): BM=128 (8 warps x 16 rows), Dh=64
// pure fp16 1-term. KV stages of 128 rows {Kh,Vh} (36.9KB), 3-slot ring,
// each stage consumed as two BN=64 sub-iterations sharing one wait+sync.
// Fully-masked diagonal sub-blocks skipped per-warp.
// smem 110592 -> 2 CTAs/SM.
// ---------------------------------------------------------------------------
#define FROW    144
#define KTILE2  18432              // 128 rows * 144 B (per matrix)
#define KVSTG2  36864              // 2 * KTILE2 (Kh,Vh)
#define FSTG2   3
#define FSMEM   (FSTG2 * KVSTG2)   // 110592

__global__ __launch_bounds__(256, 2)
void flash_mma(const __half* __restrict__ Qh_g,
               const __half* __restrict__ Kh_g,
               const __half* __restrict__ Vh_g,
               __half* __restrict__ OhP)
{
    extern __shared__ __align__(128) char fsm[];
    const uint32_t sb = s2u(fsm);

    const int tid  = threadIdx.x;
    const int lane = tid & 31;
    const int w    = tid >> 5;
    const int qi   = gridDim.x - 1 - blockIdx.x;   // longest CTAs first
    const int qb   = qi * 128;
    const int h    = blockIdx.y;
    const int b    = blockIdx.z;
    const int kh   = h >> 2;

    const size_t qoff  = (((size_t)b * HQ + h) * SS + qb) * 64;
    const size_t kvrow = ((size_t)b * HKV + kh) * SS;

    const uint32_t a_off =
        (uint32_t)((w * 16 + (lane & 15)) * FROW + (lane >> 4) * 16);
    const uint32_t kb_off =
        (uint32_t)(((lane >> 4) * 8 + (lane & 7)) * FROW + ((lane >> 3) & 1) * 16);
    const uint32_t v_off =
        (uint32_t)((lane & 15) * FROW + (lane >> 4) * 16);

    // ---- prologue: Q staged through slot 0's K region ----
#pragma unroll
    for (int i = 0; i < 4; ++i) {
        int idx = tid + 256 * i;
        int row = idx >> 3;
        int seg = idx & 7;
        uint32_t d = sb + row * FROW + seg * 16;
        CP_ASYNC16(d, Qh_g + qoff + row * 64 + seg * 8);
    }
    asm volatile("cp.async.commit_group;");
    asm volatile("cp.async.wait_group 0;");
    __syncthreads();

    uint32_t qh[4][4];
#pragma unroll
    for (int kc = 0; kc < 4; ++kc)
        LDM4(qh[kc], sb + a_off + kc * 32);
    __syncthreads();   // all warps own Q frags before slot 0 is recycled

    auto load_kv = [&](int s, int j0) {
        const __half* srcs[2] = { Kh_g, Vh_g };
        const size_t off = (kvrow + j0) * 64;
#pragma unroll
        for (int i = 0; i < 8; ++i) {
            int idx = tid + 256 * i;
            int mat = idx >> 10;
            int rem = idx & 1023;
            int row = rem >> 3;
            int seg = rem & 7;
            uint32_t d = sb + s * KVSTG2 + mat * KTILE2 + row * FROW + seg * 16;
            CP_ASYNC16(d, srcs[mat] + off + row * 64 + seg * 8);
        }
        asm volatile("cp.async.commit_group;");
    };

    const int nb = qi + 1;          // 128-row KV blocks (BM == BN2 == 128)
    load_kv(0, 0);
    if (nb > 1) load_kv(1, 128);

    float o[8][4];
#pragma unroll
    for (int j = 0; j < 8; ++j)
#pragma unroll
        for (int r = 0; r < 4; ++r) o[j][r] = 0.f;
    float mi[2] = { -1e30f, -1e30f };
    float li[2] = { 0.f, 0.f };

    const int row0    = qb + w * 16 + (lane >> 2);
    const int row_max = qb + w * 16 + 15;

    for (int it = 0; it < nb; ++it) {
        if (it + 1 < nb) {
            asm volatile("cp.async.wait_group 1;");
        } else {
            asm volatile("cp.async.wait_group 0;");
        }
        __syncthreads();
        if (it + 2 < nb) load_kv((it + 2) % FSTG2, (it + 2) * 128);

        const uint32_t kvb = sb + (it % FSTG2) * KVSTG2;

#pragma unroll
        for (int sj = 0; sj < 2; ++sj) {
            const int j0 = it * 128 + sj * 64;
            if (j0 > row_max) continue;   // fully-masked sub-block: skip

            const uint32_t kbase = kvb + (uint32_t)(sj * 64) * FROW;

            // ---- S = Q.K^T ----
            float s[8][4];
#pragma unroll
            for (int j = 0; j < 8; ++j)
#pragma unroll
                for (int r = 0; r < 4; ++r) s[j][r] = 0.f;

#pragma unroll
            for (int kc = 0; kc < 4; ++kc) {
                uint32_t bh[4][4];
#pragma unroll
                for (int j2 = 0; j2 < 4; ++j2) {
                    LDM4(bh[j2], kbase + j2 * (16 * FROW) + kb_off + kc * 32);
                }
#pragma unroll
                for (int j = 0; j < 8; ++j) {
                    const uint32_t* bhp = &bh[j >> 1][(j & 1) * 2];
                    MMA_F16(s[j], qh[kc], bhp[0], bhp[1]);
                }
            }

            // ---- causal mask ----
            if (j0 + 63 > qb + w * 16) {
#pragma unroll
                for (int j = 0; j < 8; ++j)
#pragma unroll
                    for (int r = 0; r < 4; ++r) {
                        int col = j0 + j * 8 + (lane & 3) * 2 + (r & 1);
                        int row = row0 + (r >> 1) * 8;
                        if (col > row) s[j][r] = -1e30f;
                    }
            }

            // ---- online softmax ----
#pragma unroll
            for (int h2 = 0; h2 < 2; ++h2) {
                float mt = -1e30f;
#pragma unroll
                for (int j = 0; j < 8; ++j) {
                    mt = fmaxf(mt, s[j][h2 * 2]);
                    mt = fmaxf(mt, s[j][h2 * 2 + 1]);
                }
                mt = fmaxf(mt, __shfl_xor_sync(0xffffffffu, mt, 1));
                mt = fmaxf(mt, __shfl_xor_sync(0xffffffffu, mt, 2));
                float mnew  = fmaxf(mi[h2], mt);
                float alpha = __expf(mi[h2] - mnew);
                mi[h2] = mnew;
                float sum = 0.f;
#pragma unroll
                for (int j = 0; j < 8; ++j) {
                    float p0 = __expf(s[j][h2 * 2]     - mnew);
                    float p1 = __expf(s[j][h2 * 2 + 1] - mnew);
                    s[j][h2 * 2]     = p0;
                    s[j][h2 * 2 + 1] = p1;
                    sum += p0 + p1;
                    o[j][h2 * 2]     *= alpha;
                    o[j][h2 * 2 + 1] *= alpha;
                }
                sum += __shfl_xor_sync(0xffffffffu, sum, 1);
                sum += __shfl_xor_sync(0xffffffffu, sum, 2);
                li[h2] = li[h2] * alpha + sum;
            }

            // ---- P fragments ----
            uint32_t ph[4][4];
#pragma unroll
            for (int kc = 0; kc < 4; ++kc) {
                const int jt = 2 * kc;
                ph[kc][0] = pack_h2(s[jt][0],     s[jt][1]);
                ph[kc][1] = pack_h2(s[jt][2],     s[jt][3]);
                ph[kc][2] = pack_h2(s[jt + 1][0], s[jt + 1][1]);
                ph[kc][3] = pack_h2(s[jt + 1][2], s[jt + 1][3]);
            }

            // ---- O += P.V ----
            const uint32_t vbase = kvb + KTILE2 + (uint32_t)(sj * 64) * FROW;
#pragma unroll
            for (int kc = 0; kc < 4; ++kc) {
#pragma unroll
                for (int np = 0; np < 4; ++np) {
                    uint32_t vh4[4];
                    LDM4T(vh4, vbase + kc * (16 * FROW) + v_off + np * 32);
                    MMA_F16(o[2 * np],     ph[kc], vh4[0], vh4[1]);
                    MMA_F16(o[2 * np + 1], ph[kc], vh4[2], vh4[3]);
                }
            }
        }
    }

    // ---- finalize: fp16 attention output (flat [b][s][h*64+d]) ----
    float inv0 = 1.0f / li[0];
    float inv1 = 1.0f / li[1];
#pragma unroll
    for (int j = 0; j < 8; ++j) {
        const int col = j * 8 + (lane & 3) * 2;
        size_t base0 = ((size_t)(b * SS + row0)) * DD + h * 64 + col;
        size_t base1 = ((size_t)(b * SS + row0 + 8)) * DD + h * 64 + col;
        *reinterpret_cast<__half2*>(OhP + base0) =
            __floats2half2_rn(o[j][0] * inv0, o[j][1] * inv0);
        *reinterpret_cast<__half2*>(OhP + base1) =
            __floats2half2_rn(o[j][2] * inv1, o[j][3] * inv1);
    }
}

// ---------------------------------------------------------------------------
// Host
// ---------------------------------------------------------------------------
extern "C" void kernel_launch(void* const* d_in, const int* in_sizes, int n_in,
                              void* d_out, int out_size)
{
    const float* x  = (const float*)d_in[0];
    const float* Wq = (const float*)d_in[1];
    const float* Wk = (const float*)d_in[2];
    const float* Wv = (const float*)d_in[3];
    const float* Wo = (const float*)d_in[4];
    float* out = (float*)d_out;

    __half *Xh, *Wqh, *Wkh, *Wvh, *Woh, *Oh;
    __half *Qbh, *Kbh, *Vbh;
    cudaGetSymbolAddress((void**)&Xh, g_Xh);
    cudaGetSymbolAddress((void**)&Wqh, g_Wqh);
    cudaGetSymbolAddress((void**)&Wkh, g_Wkh);
    cudaGetSymbolAddress((void**)&Wvh, g_Wvh);
    cudaGetSymbolAddress((void**)&Woh, g_Woh);
    cudaGetSymbolAddress((void**)&Oh, g_Oh);
    cudaGetSymbolAddress((void**)&Qbh, g_Qbh);
    cudaGetSymbolAddress((void**)&Kbh, g_Kbh);
    cudaGetSymbolAddress((void**)&Vbh, g_Vbh);

    const int SMEM_DYN = GSTG * STAGEB;   // 98304 -> 2 CTAs/SM
    cudaFuncSetAttribute(qkv_gemm, cudaFuncAttributeMaxDynamicSharedMemorySize, SMEM_DYN);
    cudaFuncSetAttribute(wo_gemm,  cudaFuncAttributeMaxDynamicSharedMemorySize, SMEM_DYN);
    cudaFuncSetAttribute(flash_mma, cudaFuncAttributeMaxDynamicSharedMemorySize, FSMEM);

    // single merged convert launch
    {
        SplitJobs jobs;
        jobs.in[0] = (const float4*)x;  jobs.hi[0] = (__half2*)Xh;
        jobs.in[1] = (const float4*)Wq; jobs.hi[1] = (__half2*)Wqh;
        jobs.in[2] = (const float4*)Wk; jobs.hi[2] = (__half2*)Wkh;
        jobs.in[3] = (const float4*)Wv; jobs.hi[3] = (__half2*)Wvh;
        jobs.in[4] = (const float4*)Wo; jobs.hi[4] = (__half2*)Woh;
        int n4s[5] = { BB * SS * DD / 4, HQ * DH * DD / 4, HKV * DH * DD / 4,
                       HKV * DH * DD / 4, DD * DD / 4 };
        int cum = 0;
        for (int k = 0; k < 5; ++k) { cum += n4s[k] / 256; jobs.blk_end[k] = cum; }
        split_all<<<cum, 256>>>(jobs);
    }

    // merged QKV projection (fused RoPE/scale/convert epilogue)
    qkv_gemm<<<dim3(24, 32), 128, SMEM_DYN>>>(Xh, Wqh, Wkh, Wvh, Qbh, Kbh, Vbh);

    // MMA flash attention (causal), outputs fp16
    flash_mma<<<dim3(SS / 128, HQ, BB), 256, FSMEM>>>(Qbh, Kbh, Vbh, Oh);

    // output projection -> fp32 result
    wo_gemm<<<dim3(16, 32), 128, SMEM_DYN>>>(Oh, Woh, out);
}

// round 16
// speedup vs baseline: 1.0636x; 1.0636x over previous
#include <cuda_runtime.h>
#include <cuda_fp16.h>
#include <math.h>
#include <stdint.h>

#define BB   2
#define SS   2048
#define DD   2048
#define HQ   32
#define HKV  8
#define DH   64
#define KDIM 2048

// ---------------------------------------------------------------------------
// Scratch (allocation-free rule: __device__ globals) — pure fp16 pipeline
// ---------------------------------------------------------------------------
__device__ __half g_Xh[(size_t)BB * SS * DD];
__device__ __half g_Wqh[(size_t)HQ * DH * DD];
__device__ __half g_Wkh[(size_t)HKV * DH * DD];
__device__ __half g_Wvh[(size_t)HKV * DH * DD];
__device__ __half g_Woh[(size_t)DD * DD];
__device__ __half g_Oh[(size_t)BB * SS * DD];

__device__ __half g_Qbh[(size_t)BB * HQ  * SS * DH];
__device__ __half g_Kbh[(size_t)BB * HKV * SS * DH];
__device__ __half g_Vbh[(size_t)BB * HKV * SS * DH];

// ---------------------------------------------------------------------------
// helpers
// ---------------------------------------------------------------------------
__device__ __forceinline__ uint32_t s2u(const void* p) {
    uint32_t r;
    asm("{ .reg .u64 t; cvta.to.shared.u64 t, %1; cvt.u32.u64 %0, t; }"
        : "=r"(r) : "l"(p));
    return r;
}

#define LDM4(r, addr)                                                         \
    asm volatile("ldmatrix.sync.aligned.m8n8.x4.shared.b16 {%0,%1,%2,%3}, [%4];" \
        : "=r"((r)[0]), "=r"((r)[1]), "=r"((r)[2]), "=r"((r)[3]) : "r"(addr))

#define LDM4T(r, addr)                                                        \
    asm volatile("ldmatrix.sync.aligned.m8n8.x4.trans.shared.b16 {%0,%1,%2,%3}, [%4];" \
        : "=r"((r)[0]), "=r"((r)[1]), "=r"((r)[2]), "=r"((r)[3]) : "r"(addr))

#define MMA_F16(c, a, b0, b1)                                                 \
    asm volatile("mma.sync.aligned.m16n8k16.row.col.f32.f16.f16.f32 "         \
        "{%0,%1,%2,%3}, {%4,%5,%6,%7}, {%8,%9}, {%0,%1,%2,%3};"               \
        : "+f"((c)[0]), "+f"((c)[1]), "+f"((c)[2]), "+f"((c)[3])              \
        : "r"((a)[0]), "r"((a)[1]), "r"((a)[2]), "r"((a)[3]), "r"(b0), "r"(b1))

#define CP_ASYNC16(dst, src)                                                  \
    asm volatile("cp.async.cg.shared.global [%0], [%1], 16;" :: "r"(dst), "l"(src))

__device__ __forceinline__ uint32_t pack_h2(float a, float b) {
    __half2 t = __floats2half2_rn(a, b);
    return *reinterpret_cast<uint32_t*>(&t);
}

// ---------------------------------------------------------------------------
// merged input converts: one launch, fp32 -> fp16 for all five inputs
// ---------------------------------------------------------------------------
struct SplitJobs {
    const float4* in[5];
    __half2* hi[5];
    int blk_end[5];
};

__global__ void split_all(SplitJobs jobs)
{
    int bx = blockIdx.x;
    int job = 0;
#pragma unroll
    for (int k = 0; k < 5; ++k)
        if (bx >= jobs.blk_end[k]) job = k + 1;
    int blk0 = (job == 0) ? 0 : jobs.blk_end[job - 1];
    int i = (bx - blk0) * blockDim.x + threadIdx.x;

    float4 a = jobs.in[job][i];
    jobs.hi[job][2 * i + 0] = __floats2half2_rn(a.x, a.y);
    jobs.hi[job][2 * i + 1] = __floats2half2_rn(a.z, a.w);
}

// ---------------------------------------------------------------------------
// core fp16 MMA loop (CTA 128x128x2048), 1-term  [round-14 proven version]
// 4 warps, warp tile 64x64. Stage = {Ah, Bh} = 16KB.
// XOR-swizzled smem (64B rows), 6-stage ring, depth-3 prefetch, 1 sync/iter,
// 96KB -> 2 CTAs/SM.
// ---------------------------------------------------------------------------
#define MATB   8192                 // 128 rows * 64 B
#define STAGEB 16384                // 2 * MATB
#define GSTG   6
#define KITERS (KDIM / 32)

struct GemmCore {
    float c[4][8][4];
};

__device__ __forceinline__ void gemm_mainloop(
    uint32_t sb, int tid, int lane, int wm, int wn,
    const __half* Ah_g, const __half* Bh_g,
    int m0, int n0, GemmCore& g)
{
#pragma unroll
    for (int i = 0; i < 4; ++i)
#pragma unroll
        for (int j = 0; j < 8; ++j)
#pragma unroll
            for (int r = 0; r < 4; ++r) g.c[i][j][r] = 0.f;

    const int a_row = wm * 64 + (lane & 15);
    const uint32_t a_base = (uint32_t)a_row * 64;
    const uint32_t a_swz  = (uint32_t)(((lane >> 4) ^ ((a_row >> 1) & 3)) << 4);

    const int b_row = wn * 64 + (lane >> 4) * 8 + (lane & 7);
    const uint32_t b_base = (uint32_t)b_row * 64;
    const uint32_t b_swz  = (uint32_t)((((lane >> 3) & 1) ^ ((b_row >> 1) & 3)) << 4);

    const __half* srcs[2] = { Ah_g, Bh_g };
    const int rowbase[2] = { m0, n0 };

    auto load_stage = [&](int s, int k0) {
#pragma unroll
        for (int i = 0; i < 8; ++i) {
            const int idx = tid + 128 * i;
            const int mat = idx >> 9;
            const int rem = idx & 511;
            const int row = rem >> 2;
            const int seg = rem & 3;
            uint32_t d = sb + s * STAGEB + mat * MATB + row * 64 +
                         ((seg ^ ((row >> 1) & 3)) << 4);
            const __half* p =
                srcs[mat] + (size_t)(rowbase[mat] + row) * KDIM + k0 + seg * 8;
            CP_ASYNC16(d, p);
        }
        asm volatile("cp.async.commit_group;");
    };

    load_stage(0, 0);
    load_stage(1, 32);
    load_stage(2, 64);

    for (int it = 0; it < KITERS; ++it) {
        if (it + 2 < KITERS) {
            asm volatile("cp.async.wait_group 2;");
        } else {
            asm volatile("cp.async.wait_group 0;");
        }
        __syncthreads();
        if (it + 3 < KITERS) {
            load_stage((it + 3) % GSTG, (it + 3) * 32);
        }

        const uint32_t st = sb + (it % GSTG) * STAGEB;
#pragma unroll
        for (int kk = 0; kk < 2; ++kk) {
            const uint32_t ksw = (uint32_t)(kk << 5);
            uint32_t bh[4][4];
#pragma unroll
            for (int j2 = 0; j2 < 4; ++j2) {
                LDM4(bh[j2], st + MATB + b_base + j2 * 1024 + (b_swz ^ ksw));
            }
#pragma unroll
            for (int i = 0; i < 4; ++i) {
                uint32_t ah[4];
                LDM4(ah, st + a_base + i * 1024 + (a_swz ^ ksw));
#pragma unroll
                for (int j = 0; j < 8; ++j) {
                    const uint32_t* bhp = &bh[j >> 1][(j & 1) * 2];
                    MMA_F16(g.c[i][j], ah, bhp[0], bhp[1]);
                }
            }
        }
    }
}

// ---------------------------------------------------------------------------
// merged QKV projection: grid (24, 32), 128 threads, all 1-term
// ---------------------------------------------------------------------------
__global__ __launch_bounds__(128, 2)
void qkv_gemm(const __half* __restrict__ Xh_g,
              const __half* __restrict__ Wqh_g,
              const __half* __restrict__ Wkh_g,
              const __half* __restrict__ Wvh_g,
              __half* __restrict__ Qh,
              __half* __restrict__ Kh,
              __half* __restrict__ Vh)
{
    extern __shared__ __align__(128) char smem[];
    const uint32_t sb = s2u(smem);

    const int tid  = threadIdx.x;
    const int lane = tid & 31;
    const int w    = tid >> 5;
    const int wm   = w & 1;
    const int wn   = w >> 1;
    const int bx   = blockIdx.x;
    const int m0   = blockIdx.y * 128;

    const __half *Bh_g;
    __half *dH;
    int n0, Hn;
    bool rope;
    float scale;
    if (bx < 16) {
        Bh_g = Wqh_g; dH = Qh;
        n0 = bx * 128; Hn = HQ; rope = true; scale = 0.125f;
    } else if (bx < 20) {
        Bh_g = Wkh_g; dH = Kh;
        n0 = (bx - 16) * 128; Hn = HKV; rope = true; scale = 1.0f;
    } else {
        Bh_g = Wvh_g; dH = Vh;
        n0 = (bx - 20) * 128; Hn = HKV; rope = false; scale = 1.0f;
    }

    GemmCore g;
    gemm_mainloop(sb, tid, lane, wm, wn, Xh_g, Bh_g, m0, n0, g);

#pragma unroll
    for (int i = 0; i < 4; ++i) {
        const int r0 = m0 + wm * 64 + i * 16 + (lane >> 2);
#pragma unroll
        for (int j = 0; j < 8; ++j) {
            const int col = n0 + wn * 64 + j * 8 + (lane & 3) * 2;
#pragma unroll
            for (int half = 0; half < 2; ++half) {
                const int row = r0 + half * 8;
                float x1 = g.c[i][j][half * 2];
                float x2 = g.c[i][j][half * 2 + 1];
                const int bidx = row >> 11;
                const int sRow = row & (SS - 1);
                const int hh = col >> 6, d0 = col & 63;
                size_t base = ((((size_t)bidx * Hn + hh) * SS + sRow) << 6) + d0;
                if (rope) {
                    float inv = exp2f(-(float)d0 * (13.287712379549449f / 64.0f));
                    float sn, cs;
                    sincosf((float)sRow * inv, &sn, &cs);
                    float y1 = x1 * cs - x2 * sn;
                    float y2 = x1 * sn + x2 * cs;
                    x1 = y1 * scale;
                    x2 = y2 * scale;
                }
                *reinterpret_cast<__half2*>(dH + base) =
                    __floats2half2_rn(x1, x2);
            }
        }
    }
}

// ---------------------------------------------------------------------------
// output projection (1-term fp16): fp32 flat result, 128 threads
// ---------------------------------------------------------------------------
__global__ __launch_bounds__(128, 2)
void wo_gemm(const __half* __restrict__ Ah_g,
             const __half* __restrict__ Bh_g,
             float* __restrict__ dst)
{
    extern __shared__ __align__(128) char smem[];
    const uint32_t sb = s2u(smem);

    const int tid  = threadIdx.x;
    const int lane = tid & 31;
    const int w    = tid >> 5;
    const int wm   = w & 1;
    const int wn   = w >> 1;
    const int m0   = blockIdx.y * 128;
    const int n0   = blockIdx.x * 128;

    GemmCore g;
    gemm_mainloop(sb, tid, lane, wm, wn, Ah_g, Bh_g, m0, n0, g);

#pragma unroll
    for (int i = 0; i < 4; ++i) {
        const int r0 = m0 + wm * 64 + i * 16 + (lane >> 2);
#pragma unroll
        for (int j = 0; j < 8; ++j) {
            const int col = n0 + wn * 64 + j * 8 + (lane & 3) * 2;
#pragma unroll
            for (int half = 0; half < 2; ++half) {
                const int row = r0 + half * 8;
                *reinterpret_cast<float2*>(dst + (size_t)row * DD + col) =
                    make_float2(g.c[i][j][half * 2], g.c[i][j][half * 2 + 1]);
            }
        }
    }
}

// ---------------------------------------------------------------------------
// MMA flash attention (causal, GQA): BM=128 (8 warps x 16 rows), BN=64, Dh=64
// pure fp16 1-term QK and PV. 6-stage KV ring of 18KB slots {Kh,Vh};
// Q (18KB) staged through slot 0. smem 110592 -> 2 CTAs/SM.
// Per-warp skip of fully-masked diagonal blocks.
// ---------------------------------------------------------------------------
#define FROW   144
#define FTILE  9216                // 64 rows * 144 B (per matrix)
#define KVSTG  18432               // 2 * FTILE (Kh,Vh)
#define FSTG   6
#define FSMEM  (FSTG * KVSTG)      // 110592

__global__ __launch_bounds__(256, 2)
void flash_mma(const __half* __restrict__ Qh_g,
               const __half* __restrict__ Kh_g,
               const __half* __restrict__ Vh_g,
               __half* __restrict__ OhP)
{
    extern __shared__ __align__(128) char fsm[];
    const uint32_t sb = s2u(fsm);

    const int tid  = threadIdx.x;
    const int lane = tid & 31;
    const int w    = tid >> 5;
    const int qi   = gridDim.x - 1 - blockIdx.x;   // longest CTAs first
    const int qb   = qi * 128;
    const int h    = blockIdx.y;
    const int b    = blockIdx.z;
    const int kh   = h >> 2;

    const size_t qoff  = (((size_t)b * HQ + h) * SS + qb) * 64;
    const size_t kvrow = ((size_t)b * HKV + kh) * SS;

    const uint32_t a_off =
        (uint32_t)((w * 16 + (lane & 15)) * FROW + (lane >> 4) * 16);
    const uint32_t kb_off =
        (uint32_t)(((lane >> 4) * 8 + (lane & 7)) * FROW + ((lane >> 3) & 1) * 16);
    const uint32_t v_off =
        (uint32_t)((lane & 15) * FROW + (lane >> 4) * 16);

    // ---- prologue: Q staged through slot 0 (one ring slot) ----
#pragma unroll
    for (int i = 0; i < 4; ++i) {
        int idx = tid + 256 * i;
        int row = idx >> 3;
        int seg = idx & 7;
        uint32_t d = sb + row * FROW + seg * 16;
        CP_ASYNC16(d, Qh_g + qoff + row * 64 + seg * 8);
    }
    asm volatile("cp.async.commit_group;");
    asm volatile("cp.async.wait_group 0;");
    __syncthreads();

    uint32_t qh[4][4];
#pragma unroll
    for (int kc = 0; kc < 4; ++kc)
        LDM4(qh[kc], sb + a_off + kc * 32);
    __syncthreads();   // all warps own Q frags before slot 0 is recycled

    auto load_kv = [&](int s, int j0) {
        const __half* srcs[2] = { Kh_g, Vh_g };
        const size_t off = (kvrow + j0) * 64;
#pragma unroll
        for (int i = 0; i < 4; ++i) {
            int idx = tid + 256 * i;
            int mat = idx >> 9;
            int rem = idx & 511;
            int row = rem >> 3;
            int seg = rem & 7;
            uint32_t d = sb + s * KVSTG + mat * FTILE + row * FROW + seg * 16;
            CP_ASYNC16(d, srcs[mat] + off + row * 64 + seg * 8);
        }
        asm volatile("cp.async.commit_group;");
    };

    const int nb = qb / 64 + 2;
    load_kv(0, 0);
    if (nb > 1) load_kv(1, 64);
    if (nb > 2) load_kv(2, 128);

    float o[8][4];
#pragma unroll
    for (int j = 0; j < 8; ++j)
#pragma unroll
        for (int r = 0; r < 4; ++r) o[j][r] = 0.f;
    float mi[2] = { -1e30f, -1e30f };
    float li[2] = { 0.f, 0.f };

    const int row0    = qb + w * 16 + (lane >> 2);
    const int row_max = qb + w * 16 + 15;

    for (int it = 0; it < nb; ++it) {
        if (it + 2 < nb) {
            asm volatile("cp.async.wait_group 2;");
        } else {
            asm volatile("cp.async.wait_group 0;");
        }
        __syncthreads();
        if (it + 3 < nb) load_kv((it + 3) % FSTG, (it + 3) * 64);

        const int j0 = it * 64;
        if (j0 > row_max) continue;   // fully-masked diagonal block: skip (per-warp)

        const uint32_t kvb = sb + (it % FSTG) * KVSTG;

        // ---- S = Q.K^T (1-term) ----
        float s[8][4];
#pragma unroll
        for (int j = 0; j < 8; ++j)
#pragma unroll
            for (int r = 0; r < 4; ++r) s[j][r] = 0.f;

#pragma unroll
        for (int kc = 0; kc < 4; ++kc) {
            uint32_t bh[4][4];
#pragma unroll
            for (int j2 = 0; j2 < 4; ++j2) {
                LDM4(bh[j2], kvb + j2 * (16 * FROW) + kb_off + kc * 32);
            }
#pragma unroll
            for (int j = 0; j < 8; ++j) {
                const uint32_t* bhp = &bh[j >> 1][(j & 1) * 2];
                MMA_F16(s[j], qh[kc], bhp[0], bhp[1]);
            }
        }

        // ---- causal mask ----
        if (j0 + 63 > qb + w * 16) {
#pragma unroll
            for (int j = 0; j < 8; ++j)
#pragma unroll
                for (int r = 0; r < 4; ++r) {
                    int col = j0 + j * 8 + (lane & 3) * 2 + (r & 1);
                    int row = row0 + (r >> 1) * 8;
                    if (col > row) s[j][r] = -1e30f;
                }
        }

        // ---- online softmax ----
#pragma unroll
        for (int h2 = 0; h2 < 2; ++h2) {
            float mt = -1e30f;
#pragma unroll
            for (int j = 0; j < 8; ++j) {
                mt = fmaxf(mt, s[j][h2 * 2]);
                mt = fmaxf(mt, s[j][h2 * 2 + 1]);
            }
            mt = fmaxf(mt, __shfl_xor_sync(0xffffffffu, mt, 1));
            mt = fmaxf(mt, __shfl_xor_sync(0xffffffffu, mt, 2));
            float mnew  = fmaxf(mi[h2], mt);
            float alpha = __expf(mi[h2] - mnew);
            mi[h2] = mnew;
            float sum = 0.f;
#pragma unroll
            for (int j = 0; j < 8; ++j) {
                float p0 = __expf(s[j][h2 * 2]     - mnew);
                float p1 = __expf(s[j][h2 * 2 + 1] - mnew);
                s[j][h2 * 2]     = p0;
                s[j][h2 * 2 + 1] = p1;
                sum += p0 + p1;
                o[j][h2 * 2]     *= alpha;
                o[j][h2 * 2 + 1] *= alpha;
            }
            sum += __shfl_xor_sync(0xffffffffu, sum, 1);
            sum += __shfl_xor_sync(0xffffffffu, sum, 2);
            li[h2] = li[h2] * alpha + sum;
        }

        // ---- P fragments ----
        uint32_t ph[4][4];
#pragma unroll
        for (int kc = 0; kc < 4; ++kc) {
            const int jt = 2 * kc;
            ph[kc][0] = pack_h2(s[jt][0],     s[jt][1]);
            ph[kc][1] = pack_h2(s[jt][2],     s[jt][3]);
            ph[kc][2] = pack_h2(s[jt + 1][0], s[jt + 1][1]);
            ph[kc][3] = pack_h2(s[jt + 1][2], s[jt + 1][3]);
        }

        // ---- O += P.V (1-term) ----
        const uint32_t vbase = kvb + FTILE;
#pragma unroll
        for (int kc = 0; kc < 4; ++kc) {
#pragma unroll
            for (int np = 0; np < 4; ++np) {
                uint32_t vh4[4];
                LDM4T(vh4, vbase + kc * (16 * FROW) + v_off + np * 32);
                MMA_F16(o[2 * np],     ph[kc], vh4[0], vh4[1]);
                MMA_F16(o[2 * np + 1], ph[kc], vh4[2], vh4[3]);
            }
        }
    }

    // ---- finalize: fp16 attention output (flat [b][s][h*64+d]) ----
    float inv0 = 1.0f / li[0];
    float inv1 = 1.0f / li[1];
#pragma unroll
    for (int j = 0; j < 8; ++j) {
        const int col = j * 8 + (lane & 3) * 2;
        size_t base0 = ((size_t)(b * SS + row0)) * DD + h * 64 + col;
        size_t base1 = ((size_t)(b * SS + row0 + 8)) * DD + h * 64 + col;
        *reinterpret_cast<__half2*>(OhP + base0) =
            __floats2half2_rn(o[j][0] * inv0, o[j][1] * inv0);
        *reinterpret_cast<__half2*>(OhP + base1) =
            __floats2half2_rn(o[j][2] * inv1, o[j][3] * inv1);
    }
}

// ---------------------------------------------------------------------------
// Host
// ---------------------------------------------------------------------------
extern "C" void kernel_launch(void* const* d_in, const int* in_sizes, int n_in,
                              void* d_out, int out_size)
{
    const float* x  = (const float*)d_in[0];
    const float* Wq = (const float*)d_in[1];
    const float* Wk = (const float*)d_in[2];
    const float* Wv = (const float*)d_in[3];
    const float* Wo = (const float*)d_in[4];
    float* out = (float*)d_out;

    __half *Xh, *Wqh, *Wkh, *Wvh, *Woh, *Oh;
    __half *Qbh, *Kbh, *Vbh;
    cudaGetSymbolAddress((void**)&Xh, g_Xh);
    cudaGetSymbolAddress((void**)&Wqh, g_Wqh);
    cudaGetSymbolAddress((void**)&Wkh, g_Wkh);
    cudaGetSymbolAddress((void**)&Wvh, g_Wvh);
    cudaGetSymbolAddress((void**)&Woh, g_Woh);
    cudaGetSymbolAddress((void**)&Oh, g_Oh);
    cudaGetSymbolAddress((void**)&Qbh, g_Qbh);
    cudaGetSymbolAddress((void**)&Kbh, g_Kbh);
    cudaGetSymbolAddress((void**)&Vbh, g_Vbh);

    const int SMEM_DYN = GSTG * STAGEB;   // 98304 -> 2 CTAs/SM
    cudaFuncSetAttribute(qkv_gemm, cudaFuncAttributeMaxDynamicSharedMemorySize, SMEM_DYN);
    cudaFuncSetAttribute(wo_gemm,  cudaFuncAttributeMaxDynamicSharedMemorySize, SMEM_DYN);
    cudaFuncSetAttribute(flash_mma, cudaFuncAttributeMaxDynamicSharedMemorySize, FSMEM);

    // single merged convert launch
    {
        SplitJobs jobs;
        jobs.in[0] = (const float4*)x;  jobs.hi[0] = (__half2*)Xh;
        jobs.in[1] = (const float4*)Wq; jobs.hi[1] = (__half2*)Wqh;
        jobs.in[2] = (const float4*)Wk; jobs.hi[2] = (__half2*)Wkh;
        jobs.in[3] = (const float4*)Wv; jobs.hi[3] = (__half2*)Wvh;
        jobs.in[4] = (const float4*)Wo; jobs.hi[4] = (__half2*)Woh;
        int n4s[5] = { BB * SS * DD / 4, HQ * DH * DD / 4, HKV * DH * DD / 4,
                       HKV * DH * DD / 4, DD * DD / 4 };
        int cum = 0;
        for (int k = 0; k < 5; ++k) { cum += n4s[k] / 256; jobs.blk_end[k] = cum; }
        split_all<<<cum, 256>>>(jobs);
    }

    // merged QKV projection (fused RoPE/scale/convert epilogue)
    qkv_gemm<<<dim3(24, 32), 128, SMEM_DYN>>>(Xh, Wqh, Wkh, Wvh, Qbh, Kbh, Vbh);

    // MMA flash attention (causal), outputs fp16
    flash_mma<<<dim3(SS / 128, HQ, BB), 256, FSMEM>>>(Qbh, Kbh, Vbh, Oh);

    // output projection -> fp32 result
    wo_gemm<<<dim3(16, 32), 128, SMEM_DYN>>>(Oh, Woh, out);
}

// round 17
// speedup vs baseline: 1.0766x; 1.0122x over previous
#include <cuda_runtime.h>
#include <cuda_fp16.h>
#include <math.h>
#include <stdint.h>

#define BB   2
#define SS   2048
#define DD   2048
#define HQ   32
#define HKV  8
#define DH   64
#define KDIM 2048

// ---------------------------------------------------------------------------
// Scratch (allocation-free rule: __device__ globals) — pure fp16 pipeline
// ---------------------------------------------------------------------------
__device__ __half g_Xh[(size_t)BB * SS * DD];
__device__ __half g_Wqh[(size_t)HQ * DH * DD];
__device__ __half g_Wkh[(size_t)HKV * DH * DD];
__device__ __half g_Wvh[(size_t)HKV * DH * DD];
__device__ __half g_Woh[(size_t)DD * DD];
__device__ __half g_Oh[(size_t)BB * SS * DD];

__device__ __half g_Qbh[(size_t)BB * HQ  * SS * DH];
__device__ __half g_Kbh[(size_t)BB * HKV * SS * DH];
__device__ __half g_Vbh[(size_t)BB * HKV * SS * DH];

// ---------------------------------------------------------------------------
// helpers
// ---------------------------------------------------------------------------
__device__ __forceinline__ uint32_t s2u(const void* p) {
    uint32_t r;
    asm("{ .reg .u64 t; cvta.to.shared.u64 t, %1; cvt.u32.u64 %0, t; }"
        : "=r"(r) : "l"(p));
    return r;
}

#define LDM4(r, addr)                                                         \
    asm volatile("ldmatrix.sync.aligned.m8n8.x4.shared.b16 {%0,%1,%2,%3}, [%4];" \
        : "=r"((r)[0]), "=r"((r)[1]), "=r"((r)[2]), "=r"((r)[3]) : "r"(addr))

#define LDM4T(r, addr)                                                        \
    asm volatile("ldmatrix.sync.aligned.m8n8.x4.trans.shared.b16 {%0,%1,%2,%3}, [%4];" \
        : "=r"((r)[0]), "=r"((r)[1]), "=r"((r)[2]), "=r"((r)[3]) : "r"(addr))

#define MMA_F16(c, a, b0, b1)                                                 \
    asm volatile("mma.sync.aligned.m16n8k16.row.col.f32.f16.f16.f32 "         \
        "{%0,%1,%2,%3}, {%4,%5,%6,%7}, {%8,%9}, {%0,%1,%2,%3};"               \
        : "+f"((c)[0]), "+f"((c)[1]), "+f"((c)[2]), "+f"((c)[3])              \
        : "r"((a)[0]), "r"((a)[1]), "r"((a)[2]), "r"((a)[3]), "r"(b0), "r"(b1))

#define CP_ASYNC16(dst, src)                                                  \
    asm volatile("cp.async.cg.shared.global [%0], [%1], 16;" :: "r"(dst), "l"(src))

__device__ __forceinline__ uint32_t pack_h2(float a, float b) {
    __half2 t = __floats2half2_rn(a, b);
    return *reinterpret_cast<uint32_t*>(&t);
}

__device__ __forceinline__ uint32_t ex2_h2(uint32_t a) {
    uint32_t d;
    asm("ex2.approx.f16x2 %0, %1;" : "=r"(d) : "r"(a));
    return d;
}

// ---------------------------------------------------------------------------
// merged input converts: one launch, fp32 -> fp16 for all five inputs
// ---------------------------------------------------------------------------
struct SplitJobs {
    const float4* in[5];
    __half2* hi[5];
    int blk_end[5];
};

__global__ void split_all(SplitJobs jobs)
{
    int bx = blockIdx.x;
    int job = 0;
#pragma unroll
    for (int k = 0; k < 5; ++k)
        if (bx >= jobs.blk_end[k]) job = k + 1;
    int blk0 = (job == 0) ? 0 : jobs.blk_end[job - 1];
    int i = (bx - blk0) * blockDim.x + threadIdx.x;

    float4 a = jobs.in[job][i];
    jobs.hi[job][2 * i + 0] = __floats2half2_rn(a.x, a.y);
    jobs.hi[job][2 * i + 1] = __floats2half2_rn(a.z, a.w);
}

// ---------------------------------------------------------------------------
// core fp16 MMA loop (CTA 128x128x2048), 1-term  [round-14 proven version]
// ---------------------------------------------------------------------------
#define MATB   8192                 // 128 rows * 64 B
#define STAGEB 16384                // 2 * MATB
#define GSTG   6
#define KITERS (KDIM / 32)

struct GemmCore {
    float c[4][8][4];
};

__device__ __forceinline__ void gemm_mainloop(
    uint32_t sb, int tid, int lane, int wm, int wn,
    const __half* Ah_g, const __half* Bh_g,
    int m0, int n0, GemmCore& g)
{
#pragma unroll
    for (int i = 0; i < 4; ++i)
#pragma unroll
        for (int j = 0; j < 8; ++j)
#pragma unroll
            for (int r = 0; r < 4; ++r) g.c[i][j][r] = 0.f;

    const int a_row = wm * 64 + (lane & 15);
    const uint32_t a_base = (uint32_t)a_row * 64;
    const uint32_t a_swz  = (uint32_t)(((lane >> 4) ^ ((a_row >> 1) & 3)) << 4);

    const int b_row = wn * 64 + (lane >> 4) * 8 + (lane & 7);
    const uint32_t b_base = (uint32_t)b_row * 64;
    const uint32_t b_swz  = (uint32_t)((((lane >> 3) & 1) ^ ((b_row >> 1) & 3)) << 4);

    const __half* srcs[2] = { Ah_g, Bh_g };
    const int rowbase[2] = { m0, n0 };

    auto load_stage = [&](int s, int k0) {
#pragma unroll
        for (int i = 0; i < 8; ++i) {
            const int idx = tid + 128 * i;
            const int mat = idx >> 9;
            const int rem = idx & 511;
            const int row = rem >> 2;
            const int seg = rem & 3;
            uint32_t d = sb + s * STAGEB + mat * MATB + row * 64 +
                         ((seg ^ ((row >> 1) & 3)) << 4);
            const __half* p =
                srcs[mat] + (size_t)(rowbase[mat] + row) * KDIM + k0 + seg * 8;
            CP_ASYNC16(d, p);
        }
        asm volatile("cp.async.commit_group;");
    };

    load_stage(0, 0);
    load_stage(1, 32);
    load_stage(2, 64);

    for (int it = 0; it < KITERS; ++it) {
        if (it + 2 < KITERS) {
            asm volatile("cp.async.wait_group 2;");
        } else {
            asm volatile("cp.async.wait_group 0;");
        }
        __syncthreads();
        if (it + 3 < KITERS) {
            load_stage((it + 3) % GSTG, (it + 3) * 32);
        }

        const uint32_t st = sb + (it % GSTG) * STAGEB;
#pragma unroll
        for (int kk = 0; kk < 2; ++kk) {
            const uint32_t ksw = (uint32_t)(kk << 5);
            uint32_t bh[4][4];
#pragma unroll
            for (int j2 = 0; j2 < 4; ++j2) {
                LDM4(bh[j2], st + MATB + b_base + j2 * 1024 + (b_swz ^ ksw));
            }
#pragma unroll
            for (int i = 0; i < 4; ++i) {
                uint32_t ah[4];
                LDM4(ah, st + a_base + i * 1024 + (a_swz ^ ksw));
#pragma unroll
                for (int j = 0; j < 8; ++j) {
                    const uint32_t* bhp = &bh[j >> 1][(j & 1) * 2];
                    MMA_F16(g.c[i][j], ah, bhp[0], bhp[1]);
                }
            }
        }
    }
}

// ---------------------------------------------------------------------------
// merged QKV projection: grid (24, 32), 128 threads, all 1-term
// ---------------------------------------------------------------------------
__global__ __launch_bounds__(128, 2)
void qkv_gemm(const __half* __restrict__ Xh_g,
              const __half* __restrict__ Wqh_g,
              const __half* __restrict__ Wkh_g,
              const __half* __restrict__ Wvh_g,
              __half* __restrict__ Qh,
              __half* __restrict__ Kh,
              __half* __restrict__ Vh)
{
    extern __shared__ __align__(128) char smem[];
    const uint32_t sb = s2u(smem);

    const int tid  = threadIdx.x;
    const int lane = tid & 31;
    const int w    = tid >> 5;
    const int wm   = w & 1;
    const int wn   = w >> 1;
    const int bx   = blockIdx.x;
    const int m0   = blockIdx.y * 128;

    const __half *Bh_g;
    __half *dH;
    int n0, Hn;
    bool rope;
    float scale;
    if (bx < 16) {
        Bh_g = Wqh_g; dH = Qh;
        n0 = bx * 128; Hn = HQ; rope = true; scale = 0.125f;
    } else if (bx < 20) {
        Bh_g = Wkh_g; dH = Kh;
        n0 = (bx - 16) * 128; Hn = HKV; rope = true; scale = 1.0f;
    } else {
        Bh_g = Wvh_g; dH = Vh;
        n0 = (bx - 20) * 128; Hn = HKV; rope = false; scale = 1.0f;
    }

    GemmCore g;
    gemm_mainloop(sb, tid, lane, wm, wn, Xh_g, Bh_g, m0, n0, g);

#pragma unroll
    for (int i = 0; i < 4; ++i) {
        const int r0 = m0 + wm * 64 + i * 16 + (lane >> 2);
#pragma unroll
        for (int j = 0; j < 8; ++j) {
            const int col = n0 + wn * 64 + j * 8 + (lane & 3) * 2;
#pragma unroll
            for (int half = 0; half < 2; ++half) {
                const int row = r0 + half * 8;
                float x1 = g.c[i][j][half * 2];
                float x2 = g.c[i][j][half * 2 + 1];
                const int bidx = row >> 11;
                const int sRow = row & (SS - 1);
                const int hh = col >> 6, d0 = col & 63;
                size_t base = ((((size_t)bidx * Hn + hh) * SS + sRow) << 6) + d0;
                if (rope) {
                    float inv = exp2f(-(float)d0 * (13.287712379549449f / 64.0f));
                    float sn, cs;
                    sincosf((float)sRow * inv, &sn, &cs);
                    float y1 = x1 * cs - x2 * sn;
                    float y2 = x1 * sn + x2 * cs;
                    x1 = y1 * scale;
                    x2 = y2 * scale;
                }
                *reinterpret_cast<__half2*>(dH + base) =
                    __floats2half2_rn(x1, x2);
            }
        }
    }
}

// ---------------------------------------------------------------------------
// output projection (1-term fp16): fp32 flat result, 128 threads
// ---------------------------------------------------------------------------
__global__ __launch_bounds__(128, 2)
void wo_gemm(const __half* __restrict__ Ah_g,
             const __half* __restrict__ Bh_g,
             float* __restrict__ dst)
{
    extern __shared__ __align__(128) char smem[];
    const uint32_t sb = s2u(smem);

    const int tid  = threadIdx.x;
    const int lane = tid & 31;
    const int w    = tid >> 5;
    const int wm   = w & 1;
    const int wn   = w >> 1;
    const int m0   = blockIdx.y * 128;
    const int n0   = blockIdx.x * 128;

    GemmCore g;
    gemm_mainloop(sb, tid, lane, wm, wn, Ah_g, Bh_g, m0, n0, g);

#pragma unroll
    for (int i = 0; i < 4; ++i) {
        const int r0 = m0 + wm * 64 + i * 16 + (lane >> 2);
#pragma unroll
        for (int j = 0; j < 8; ++j) {
            const int col = n0 + wn * 64 + j * 8 + (lane & 3) * 2;
#pragma unroll
            for (int half = 0; half < 2; ++half) {
                const int row = r0 + half * 8;
                *reinterpret_cast<float2*>(dst + (size_t)row * DD + col) =
                    make_float2(g.c[i][j][half * 2], g.c[i][j][half * 2 + 1]);
            }
        }
    }
}

// ---------------------------------------------------------------------------
// MMA flash attention (causal, GQA): BM=128 (8 warps x 16 rows), BN=64, Dh=64
// pure fp16 1-term QK and PV. 6-stage KV ring of 18KB slots {Kh,Vh};
// Q staged through slot 0. smem 110592 -> 2 CTAs/SM.
// Per-warp skip of fully-masked diagonal blocks.
// Softmax: P fragments via ex2.approx.f16x2 (MUFU halved); sums from fp16 P.
// ---------------------------------------------------------------------------
#define FROW   144
#define FTILE  9216                // 64 rows * 144 B (per matrix)
#define KVSTG  18432               // 2 * FTILE (Kh,Vh)
#define FSTG   6
#define FSMEM  (FSTG * KVSTG)      // 110592

__global__ __launch_bounds__(256, 2)
void flash_mma(const __half* __restrict__ Qh_g,
               const __half* __restrict__ Kh_g,
               const __half* __restrict__ Vh_g,
               __half* __restrict__ OhP)
{
    extern __shared__ __align__(128) char fsm[];
    const uint32_t sb = s2u(fsm);

    const int tid  = threadIdx.x;
    const int lane = tid & 31;
    const int w    = tid >> 5;
    const int qi   = gridDim.x - 1 - blockIdx.x;   // longest CTAs first
    const int qb   = qi * 128;
    const int h    = blockIdx.y;
    const int b    = blockIdx.z;
    const int kh   = h >> 2;

    const size_t qoff  = (((size_t)b * HQ + h) * SS + qb) * 64;
    const size_t kvrow = ((size_t)b * HKV + kh) * SS;

    const uint32_t a_off =
        (uint32_t)((w * 16 + (lane & 15)) * FROW + (lane >> 4) * 16);
    const uint32_t kb_off =
        (uint32_t)(((lane >> 4) * 8 + (lane & 7)) * FROW + ((lane >> 3) & 1) * 16);
    const uint32_t v_off =
        (uint32_t)((lane & 15) * FROW + (lane >> 4) * 16);

    // ---- prologue: Q staged through slot 0 (one ring slot) ----
#pragma unroll
    for (int i = 0; i < 4; ++i) {
        int idx = tid + 256 * i;
        int row = idx >> 3;
        int seg = idx & 7;
        uint32_t d = sb + row * FROW + seg * 16;
        CP_ASYNC16(d, Qh_g + qoff + row * 64 + seg * 8);
    }
    asm volatile("cp.async.commit_group;");
    asm volatile("cp.async.wait_group 0;");
    __syncthreads();

    uint32_t qh[4][4];
#pragma unroll
    for (int kc = 0; kc < 4; ++kc)
        LDM4(qh[kc], sb + a_off + kc * 32);
    __syncthreads();   // all warps own Q frags before slot 0 is recycled

    auto load_kv = [&](int s, int j0) {
        const __half* srcs[2] = { Kh_g, Vh_g };
        const size_t off = (kvrow + j0) * 64;
#pragma unroll
        for (int i = 0; i < 4; ++i) {
            int idx = tid + 256 * i;
            int mat = idx >> 9;
            int rem = idx & 511;
            int row = rem >> 3;
            int seg = rem & 7;
            uint32_t d = sb + s * KVSTG + mat * FTILE + row * FROW + seg * 16;
            CP_ASYNC16(d, srcs[mat] + off + row * 64 + seg * 8);
        }
        asm volatile("cp.async.commit_group;");
    };

    const int nb = qb / 64 + 2;
    load_kv(0, 0);
    if (nb > 1) load_kv(1, 64);
    if (nb > 2) load_kv(2, 128);

    float o[8][4];
#pragma unroll
    for (int j = 0; j < 8; ++j)
#pragma unroll
        for (int r = 0; r < 4; ++r) o[j][r] = 0.f;
    float mi[2] = { -1e30f, -1e30f };
    float li[2] = { 0.f, 0.f };

    const int row0    = qb + w * 16 + (lane >> 2);
    const int row_max = qb + w * 16 + 15;
    const float L2E   = 1.4426950408889634f;

    for (int it = 0; it < nb; ++it) {
        if (it + 2 < nb) {
            asm volatile("cp.async.wait_group 2;");
        } else {
            asm volatile("cp.async.wait_group 0;");
        }
        __syncthreads();
        if (it + 3 < nb) load_kv((it + 3) % FSTG, (it + 3) * 64);

        const int j0 = it * 64;
        if (j0 > row_max) continue;   // fully-masked diagonal block: skip (per-warp)

        const uint32_t kvb = sb + (it % FSTG) * KVSTG;

        // ---- S = Q.K^T (1-term) ----
        float s[8][4];
#pragma unroll
        for (int j = 0; j < 8; ++j)
#pragma unroll
            for (int r = 0; r < 4; ++r) s[j][r] = 0.f;

#pragma unroll
        for (int kc = 0; kc < 4; ++kc) {
            uint32_t bh[4][4];
#pragma unroll
            for (int j2 = 0; j2 < 4; ++j2) {
                LDM4(bh[j2], kvb + j2 * (16 * FROW) + kb_off + kc * 32);
            }
#pragma unroll
            for (int j = 0; j < 8; ++j) {
                const uint32_t* bhp = &bh[j >> 1][(j & 1) * 2];
                MMA_F16(s[j], qh[kc], bhp[0], bhp[1]);
            }
        }

        // ---- causal mask ----
        if (j0 + 63 > qb + w * 16) {
#pragma unroll
            for (int j = 0; j < 8; ++j)
#pragma unroll
                for (int r = 0; r < 4; ++r) {
                    int col = j0 + j * 8 + (lane & 3) * 2 + (r & 1);
                    int row = row0 + (r >> 1) * 8;
                    if (col > row) s[j][r] = -1e30f;
                }
        }

        // ---- online softmax: max/alpha per half ----
        float mnew2[2], alpha2[2];
#pragma unroll
        for (int h2 = 0; h2 < 2; ++h2) {
            float mt = -1e30f;
#pragma unroll
            for (int j = 0; j < 8; ++j) {
                mt = fmaxf(mt, s[j][h2 * 2]);
                mt = fmaxf(mt, s[j][h2 * 2 + 1]);
            }
            mt = fmaxf(mt, __shfl_xor_sync(0xffffffffu, mt, 1));
            mt = fmaxf(mt, __shfl_xor_sync(0xffffffffu, mt, 2));
            mnew2[h2]  = fmaxf(mi[h2], mt);
            alpha2[h2] = __expf(mi[h2] - mnew2[h2]);
            mi[h2]     = mnew2[h2];
        }

        // ---- to log2 domain ----
#pragma unroll
        for (int j = 0; j < 8; ++j) {
            s[j][0] = (s[j][0] - mnew2[0]) * L2E;
            s[j][1] = (s[j][1] - mnew2[0]) * L2E;
            s[j][2] = (s[j][2] - mnew2[1]) * L2E;
            s[j][3] = (s[j][3] - mnew2[1]) * L2E;
        }

        // ---- P fragments directly via ex2.approx.f16x2 ----
        uint32_t ph[4][4];
#pragma unroll
        for (int kc = 0; kc < 4; ++kc) {
            const int jt = 2 * kc;
            ph[kc][0] = ex2_h2(pack_h2(s[jt][0],     s[jt][1]));
            ph[kc][1] = ex2_h2(pack_h2(s[jt][2],     s[jt][3]));
            ph[kc][2] = ex2_h2(pack_h2(s[jt + 1][0], s[jt + 1][1]));
            ph[kc][3] = ex2_h2(pack_h2(s[jt + 1][2], s[jt + 1][3]));
        }

        // ---- row sums from fp16 P (ALU/FMA pipes) ----
        float sum0 = 0.f, sum1 = 0.f;
#pragma unroll
        for (int kc = 0; kc < 4; ++kc) {
            float2 t;
            t = __half22float2(*reinterpret_cast<__half2*>(&ph[kc][0]));
            sum0 += t.x + t.y;
            t = __half22float2(*reinterpret_cast<__half2*>(&ph[kc][2]));
            sum0 += t.x + t.y;
            t = __half22float2(*reinterpret_cast<__half2*>(&ph[kc][1]));
            sum1 += t.x + t.y;
            t = __half22float2(*reinterpret_cast<__half2*>(&ph[kc][3]));
            sum1 += t.x + t.y;
        }
        sum0 += __shfl_xor_sync(0xffffffffu, sum0, 1);
        sum0 += __shfl_xor_sync(0xffffffffu, sum0, 2);
        sum1 += __shfl_xor_sync(0xffffffffu, sum1, 1);
        sum1 += __shfl_xor_sync(0xffffffffu, sum1, 2);
        li[0] = li[0] * alpha2[0] + sum0;
        li[1] = li[1] * alpha2[1] + sum1;

        // ---- rescale accumulators ----
#pragma unroll
        for (int j = 0; j < 8; ++j) {
            o[j][0] *= alpha2[0];
            o[j][1] *= alpha2[0];
            o[j][2] *= alpha2[1];
            o[j][3] *= alpha2[1];
        }

        // ---- O += P.V (1-term) ----
        const uint32_t vbase = kvb + FTILE;
#pragma unroll
        for (int kc = 0; kc < 4; ++kc) {
#pragma unroll
            for (int np = 0; np < 4; ++np) {
                uint32_t vh4[4];
                LDM4T(vh4, vbase + kc * (16 * FROW) + v_off + np * 32);
                MMA_F16(o[2 * np],     ph[kc], vh4[0], vh4[1]);
                MMA_F16(o[2 * np + 1], ph[kc], vh4[2], vh4[3]);
            }
        }
    }

    // ---- finalize: fp16 attention output (flat [b][s][h*64+d]) ----
    float inv0 = 1.0f / li[0];
    float inv1 = 1.0f / li[1];
#pragma unroll
    for (int j = 0; j < 8; ++j) {
        const int col = j * 8 + (lane & 3) * 2;
        size_t base0 = ((size_t)(b * SS + row0)) * DD + h * 64 + col;
        size_t base1 = ((size_t)(b * SS + row0 + 8)) * DD + h * 64 + col;
        *reinterpret_cast<__half2*>(OhP + base0) =
            __floats2half2_rn(o[j][0] * inv0, o[j][1] * inv0);
        *reinterpret_cast<__half2*>(OhP + base1) =
            __floats2half2_rn(o[j][2] * inv1, o[j][3] * inv1);
    }
}

// ---------------------------------------------------------------------------
// Host
// ---------------------------------------------------------------------------
extern "C" void kernel_launch(void* const* d_in, const int* in_sizes, int n_in,
                              void* d_out, int out_size)
{
    const float* x  = (const float*)d_in[0];
    const float* Wq = (const float*)d_in[1];
    const float* Wk = (const float*)d_in[2];
    const float* Wv = (const float*)d_in[3];
    const float* Wo = (const float*)d_in[4];
    float* out = (float*)d_out;

    __half *Xh, *Wqh, *Wkh, *Wvh, *Woh, *Oh;
    __half *Qbh, *Kbh, *Vbh;
    cudaGetSymbolAddress((void**)&Xh, g_Xh);
    cudaGetSymbolAddress((void**)&Wqh, g_Wqh);
    cudaGetSymbolAddress((void**)&Wkh, g_Wkh);
    cudaGetSymbolAddress((void**)&Wvh, g_Wvh);
    cudaGetSymbolAddress((void**)&Woh, g_Woh);
    cudaGetSymbolAddress((void**)&Oh, g_Oh);
    cudaGetSymbolAddress((void**)&Qbh, g_Qbh);
    cudaGetSymbolAddress((void**)&Kbh, g_Kbh);
    cudaGetSymbolAddress((void**)&Vbh, g_Vbh);

    const int SMEM_DYN = GSTG * STAGEB;   // 98304 -> 2 CTAs/SM
    cudaFuncSetAttribute(qkv_gemm, cudaFuncAttributeMaxDynamicSharedMemorySize, SMEM_DYN);
    cudaFuncSetAttribute(wo_gemm,  cudaFuncAttributeMaxDynamicSharedMemorySize, SMEM_DYN);
    cudaFuncSetAttribute(flash_mma, cudaFuncAttributeMaxDynamicSharedMemorySize, FSMEM);

    // single merged convert launch
    {
        SplitJobs jobs;
        jobs.in[0] = (const float4*)x;  jobs.hi[0] = (__half2*)Xh;
        jobs.in[1] = (const float4*)Wq; jobs.hi[1] = (__half2*)Wqh;
        jobs.in[2] = (const float4*)Wk; jobs.hi[2] = (__half2*)Wkh;
        jobs.in[3] = (const float4*)Wv; jobs.hi[3] = (__half2*)Wvh;
        jobs.in[4] = (const float4*)Wo; jobs.hi[4] = (__half2*)Woh;
        int n4s[5] = { BB * SS * DD / 4, HQ * DH * DD / 4, HKV * DH * DD / 4,
                       HKV * DH * DD / 4, DD * DD / 4 };
        int cum = 0;
        for (int k = 0; k < 5; ++k) { cum += n4s[k] / 256; jobs.blk_end[k] = cum; }
        split_all<<<cum, 256>>>(jobs);
    }

    // merged QKV projection (fused RoPE/scale/convert epilogue)
    qkv_gemm<<<dim3(24, 32), 128, SMEM_DYN>>>(Xh, Wqh, Wkh, Wvh, Qbh, Kbh, Vbh);

    // MMA flash attention (causal), outputs fp16
    flash_mma<<<dim3(SS / 128, HQ, BB), 256, FSMEM>>>(Qbh, Kbh, Vbh, Oh);

    // output projection -> fp32 result
    wo_gemm<<<dim3(16, 32), 128, SMEM_DYN>>>(Oh, Woh, out);
}